// round 8
// baseline (speedup 1.0000x reference)
#include <cuda_runtime.h>

#define LSEQ   2048
#define DMODEL 1024
#define NH     16
#define DKH    64
#define NHOPS  3

// ---------------------------------------------------------------------------
// Scratch (no allocation allowed -> __device__ globals). ~40 MB total.
// ---------------------------------------------------------------------------
__device__ float g_Q[LSEQ * DMODEL];
__device__ float g_K[LSEQ * DMODEL];
__device__ float g_V[LSEQ * DMODEL];
__device__ float g_ctx[LSEQ * DMODEL];
__device__ float g_cur[LSEQ * DMODEL];
__device__ float g_gate[LSEQ];
__device__ float g_rowm[NH * LSEQ];      // per (h,q) row max of scores
__device__ float g_rowscale[NH * LSEQ];  // gate[q] / sum(exp(s - m))

// ---------------------------------------------------------------------------
// Dense projection GEMM: C[2048][1024] = A[2048][1024] @ B[1024][1024] + bias
// BM=128, BN=64, BK=8, 256 threads, 8x4 per thread, register prefetch.
// ---------------------------------------------------------------------------
__global__ __launch_bounds__(256)
void gemm_proj(const float* __restrict__ A, const float* __restrict__ B,
               const float* __restrict__ bias, float* __restrict__ C)
{
    __shared__ float As[8][132];
    __shared__ float Bs[8][64];

    const int tid = threadIdx.x;
    const int tx  = tid & 15;        // output col group (0..15) -> cols tx*4..+3
    const int ty  = tid >> 4;        // output row group (0..15)
    const int rowBase = blockIdx.y * 128;
    const int colBase = blockIdx.x * 64;

    const int aRow = tid >> 1;              // 0..127
    const int aCol = (tid & 1) * 4;         // 0 or 4
    const int bRow = tid >> 5;              // 0..7
    const int bCol = (tid & 31) * 2;        // 0..62

    const float* Aptr = A + (size_t)(rowBase + aRow) * DMODEL + aCol;
    const float* Bptr = B + (size_t)bRow * DMODEL + colBase + bCol;

    float acc[8][4];
#pragma unroll
    for (int i = 0; i < 8; i++)
#pragma unroll
        for (int j = 0; j < 4; j++) acc[i][j] = 0.f;

    float4 aReg = *(const float4*)Aptr;
    float2 bReg = *(const float2*)Bptr;

    const int NT = DMODEL / 8;  // 128
    for (int kt = 0; kt < NT; kt++) {
        As[aCol + 0][aRow] = aReg.x;
        As[aCol + 1][aRow] = aReg.y;
        As[aCol + 2][aRow] = aReg.z;
        As[aCol + 3][aRow] = aReg.w;
        *(float2*)&Bs[bRow][bCol] = bReg;
        __syncthreads();
        if (kt + 1 < NT) {
            aReg = *(const float4*)(Aptr + (kt + 1) * 8);
            bReg = *(const float2*)(Bptr + (size_t)(kt + 1) * 8 * DMODEL);
        }
#pragma unroll
        for (int k = 0; k < 8; k++) {
            float4 a0 = *(const float4*)&As[k][ty * 4];
            float4 a1 = *(const float4*)&As[k][64 + ty * 4];
            float4 b  = *(const float4*)&Bs[k][tx * 4];
            float ar[8] = {a0.x, a0.y, a0.z, a0.w, a1.x, a1.y, a1.z, a1.w};
            float br[4] = {b.x, b.y, b.z, b.w};
#pragma unroll
            for (int i = 0; i < 8; i++)
#pragma unroll
                for (int j = 0; j < 4; j++)
                    acc[i][j] = fmaf(ar[i], br[j], acc[i][j]);
        }
        __syncthreads();
    }

    const int c = colBase + tx * 4;
    float4 bv = *(const float4*)&bias[c];
#pragma unroll
    for (int i = 0; i < 8; i++) {
        int r = rowBase + ((i < 4) ? (ty * 4 + i) : (64 + ty * 4 + (i - 4)));
        float4 o;
        o.x = acc[i][0] + bv.x;
        o.y = acc[i][1] + bv.y;
        o.z = acc[i][2] + bv.z;
        o.w = acc[i][3] + bv.w;
        *(float4*)&C[(size_t)r * DMODEL + c] = o;
    }
}

// ---------------------------------------------------------------------------
// Per-head score GEMM: S[h][q][k] = scale * dot(cur[q, h*64..], K[k, h*64..])
// BM=BN=128, K=64 (single tile), 256 threads, 8x8 per thread. Dynamic smem.
// Writes raw scaled scores directly into the weights output region.
// ---------------------------------------------------------------------------
__global__ __launch_bounds__(256)
void scores_kernel(const float* __restrict__ Qc, const float* __restrict__ Kc,
                   float* __restrict__ S)
{
    extern __shared__ float sm[];
    float (*As)[132] = (float(*)[132])sm;              // [64][132]
    float (*Bs)[132] = (float(*)[132])(sm + 64 * 132); // [64][132]

    const int tid = threadIdx.x;
    const int tx = tid & 15;
    const int ty = tid >> 4;
    const int h = blockIdx.z;
    const int qBase = blockIdx.y * 128;
    const int kBase = blockIdx.x * 128;

    const float* Ap = Qc + (size_t)qBase * DMODEL + h * DKH;
    const float* Bp = Kc + (size_t)kBase * DMODEL + h * DKH;

#pragma unroll
    for (int i = 0; i < 8; i++) {
        int idx = tid + i * 256;       // 0..2047
        int r   = idx >> 4;            // 0..127
        int c4  = (idx & 15) * 4;      // 0..60
        float4 a = *(const float4*)(Ap + (size_t)r * DMODEL + c4);
        As[c4 + 0][r] = a.x; As[c4 + 1][r] = a.y;
        As[c4 + 2][r] = a.z; As[c4 + 3][r] = a.w;
        float4 b = *(const float4*)(Bp + (size_t)r * DMODEL + c4);
        Bs[c4 + 0][r] = b.x; Bs[c4 + 1][r] = b.y;
        Bs[c4 + 2][r] = b.z; Bs[c4 + 3][r] = b.w;
    }
    __syncthreads();

    float acc[8][8];
#pragma unroll
    for (int i = 0; i < 8; i++)
#pragma unroll
        for (int j = 0; j < 8; j++) acc[i][j] = 0.f;

#pragma unroll 8
    for (int k = 0; k < 64; k++) {
        float4 a0 = *(const float4*)&As[k][ty * 4];
        float4 a1 = *(const float4*)&As[k][64 + ty * 4];
        float4 b0 = *(const float4*)&Bs[k][tx * 4];
        float4 b1 = *(const float4*)&Bs[k][64 + tx * 4];
        float ar[8] = {a0.x, a0.y, a0.z, a0.w, a1.x, a1.y, a1.z, a1.w};
        float br[8] = {b0.x, b0.y, b0.z, b0.w, b1.x, b1.y, b1.z, b1.w};
#pragma unroll
        for (int i = 0; i < 8; i++)
#pragma unroll
            for (int j = 0; j < 8; j++)
                acc[i][j] = fmaf(ar[i], br[j], acc[i][j]);
    }

    const float scale = 0.125f;  // 1/sqrt(64)
    float* Sp = S + ((size_t)(h * LSEQ + qBase)) * LSEQ + kBase;
#pragma unroll
    for (int i = 0; i < 8; i++) {
        int r = (i < 4) ? (ty * 4 + i) : (64 + ty * 4 + (i - 4));
        float4 o0, o1;
        o0.x = acc[i][0] * scale; o0.y = acc[i][1] * scale;
        o0.z = acc[i][2] * scale; o0.w = acc[i][3] * scale;
        o1.x = acc[i][4] * scale; o1.y = acc[i][5] * scale;
        o1.z = acc[i][6] * scale; o1.w = acc[i][7] * scale;
        *(float4*)&Sp[(size_t)r * LSEQ + tx * 4]      = o0;
        *(float4*)&Sp[(size_t)r * LSEQ + 64 + tx * 4] = o1;
    }
}

// ---------------------------------------------------------------------------
// Row stats: one warp per score row (h,q). Row held in registers (64 floats):
// single HBM read -> max, sum(exp(s-m)); store m and gate/sum.
// ---------------------------------------------------------------------------
__global__ __launch_bounds__(256)
void stats_kernel(const float* __restrict__ S)
{
    const int warp = threadIdx.x >> 5;
    const int lane = threadIdx.x & 31;
    const int row = blockIdx.x * 8 + warp;   // 0 .. NH*LSEQ-1
    const float* p = S + (size_t)row * LSEQ;

    float4 vals[16];
    float m = -1e30f;
#pragma unroll
    for (int i = 0; i < 16; i++) {
        vals[i] = *(const float4*)&p[(lane + i * 32) * 4];
        m = fmaxf(m, fmaxf(fmaxf(vals[i].x, vals[i].y), fmaxf(vals[i].z, vals[i].w)));
    }
#pragma unroll
    for (int off = 16; off > 0; off >>= 1)
        m = fmaxf(m, __shfl_xor_sync(0xffffffffu, m, off));

    float s = 0.f;
#pragma unroll
    for (int i = 0; i < 16; i++) {
        s += __expf(vals[i].x - m) + __expf(vals[i].y - m)
           + __expf(vals[i].z - m) + __expf(vals[i].w - m);
    }
#pragma unroll
    for (int off = 16; off > 0; off >>= 1)
        s += __shfl_xor_sync(0xffffffffu, s, off);

    if (lane == 0) {
        int q = row & (LSEQ - 1);
        g_rowm[row] = m;
        g_rowscale[row] = g_gate[q] / s;
    }
}

// ---------------------------------------------------------------------------
// Fused normalize + w write + ctx GEMM.
// ctx[h] (128 q-rows x 64) = w(128 x 2048) @ V[h](2048 x 64),
// where w = gate * exp(s - m) / sum is computed in registers from raw scores
// and written back IN-PLACE into the weights output (each element once).
// ---------------------------------------------------------------------------
__global__ __launch_bounds__(256)
void ctx_kernel(float* __restrict__ S, const float* __restrict__ V)
{
    __shared__ float Ws[32][132];
    __shared__ float Vs[32][64];

    const int tid = threadIdx.x;
    const int tx = tid & 15;
    const int ty = tid >> 4;
    const int h = blockIdx.y;
    const int qBase = blockIdx.x * 128;

    const int sRow0 = tid >> 3;        // 0..31
    const int sCol  = (tid & 7) * 4;   // 0..28

    float mloc[4], gloc[4];
#pragma unroll
    for (int r = 0; r < 4; r++) {
        int row = h * LSEQ + qBase + sRow0 + 32 * r;
        mloc[r] = g_rowm[row];
        gloc[r] = g_rowscale[row];
    }

    float* Sbase = S + ((size_t)(h * LSEQ + qBase)) * LSEQ;
    const float* Vp = V + h * DKH;

    float acc[8][4];
#pragma unroll
    for (int i = 0; i < 8; i++)
#pragma unroll
        for (int j = 0; j < 4; j++) acc[i][j] = 0.f;

    float4 sreg[4];
    float4 vreg[2];
#pragma unroll
    for (int r = 0; r < 4; r++)
        sreg[r] = *(const float4*)&Sbase[(size_t)(sRow0 + 32 * r) * LSEQ + sCol];
#pragma unroll
    for (int i = 0; i < 2; i++) {
        int idx = tid + i * 256;
        int vr = idx >> 4, vc = (idx & 15) * 4;
        vreg[i] = *(const float4*)&Vp[(size_t)vr * DMODEL + vc];
    }

    const int NT = LSEQ / 32;  // 64
    for (int kt = 0; kt < NT; kt++) {
        // Normalize, write w to gmem (in-place) and to smem (transposed).
#pragma unroll
        for (int r = 0; r < 4; r++) {
            int row = sRow0 + 32 * r;
            float4 s = sreg[r];
            float4 w;
            w.x = __expf(s.x - mloc[r]) * gloc[r];
            w.y = __expf(s.y - mloc[r]) * gloc[r];
            w.z = __expf(s.z - mloc[r]) * gloc[r];
            w.w = __expf(s.w - mloc[r]) * gloc[r];
            *(float4*)&Sbase[(size_t)row * LSEQ + kt * 32 + sCol] = w;
            Ws[sCol + 0][row] = w.x; Ws[sCol + 1][row] = w.y;
            Ws[sCol + 2][row] = w.z; Ws[sCol + 3][row] = w.w;
        }
#pragma unroll
        for (int i = 0; i < 2; i++) {
            int idx = tid + i * 256;
            int vr = idx >> 4, vc = (idx & 15) * 4;
            *(float4*)&Vs[vr][vc] = vreg[i];
        }
        __syncthreads();
        if (kt + 1 < NT) {
#pragma unroll
            for (int r = 0; r < 4; r++)
                sreg[r] = *(const float4*)&Sbase[(size_t)(sRow0 + 32 * r) * LSEQ
                                                 + (kt + 1) * 32 + sCol];
#pragma unroll
            for (int i = 0; i < 2; i++) {
                int idx = tid + i * 256;
                int vr = idx >> 4, vc = (idx & 15) * 4;
                vreg[i] = *(const float4*)&Vp[(size_t)((kt + 1) * 32 + vr) * DMODEL + vc];
            }
        }
#pragma unroll 8
        for (int k = 0; k < 32; k++) {
            float4 a0 = *(const float4*)&Ws[k][ty * 4];
            float4 a1 = *(const float4*)&Ws[k][64 + ty * 4];
            float4 b  = *(const float4*)&Vs[k][tx * 4];
            float ar[8] = {a0.x, a0.y, a0.z, a0.w, a1.x, a1.y, a1.z, a1.w};
            float br[4] = {b.x, b.y, b.z, b.w};
#pragma unroll
            for (int i = 0; i < 8; i++)
#pragma unroll
                for (int j = 0; j < 4; j++)
                    acc[i][j] = fmaf(ar[i], br[j], acc[i][j]);
        }
        __syncthreads();
    }

#pragma unroll
    for (int i = 0; i < 8; i++) {
        int r = qBase + ((i < 4) ? (ty * 4 + i) : (64 + ty * 4 + (i - 4)));
        float4 o;
        o.x = acc[i][0]; o.y = acc[i][1]; o.z = acc[i][2]; o.w = acc[i][3];
        *(float4*)&g_ctx[(size_t)r * DMODEL + h * DKH + tx * 4] = o;
    }
}

// ---------------------------------------------------------------------------
// Gate: g[q] = sigmoid(dot(q_row, Wg) + bg). One warp per row.
// ---------------------------------------------------------------------------
__global__ __launch_bounds__(256)
void gates_kernel(const float* __restrict__ q, const float* __restrict__ Wg,
                  const float* __restrict__ bg)
{
    const int warp = threadIdx.x >> 5;
    const int lane = threadIdx.x & 31;
    const int row = blockIdx.x * 8 + warp;
    const float* p = q + (size_t)row * DMODEL;

    float s = 0.f;
#pragma unroll
    for (int i = 0; i < 8; i++) {
        float4 a = *(const float4*)&p[(lane + i * 32) * 4];
        float4 w = *(const float4*)&Wg[(lane + i * 32) * 4];
        s += a.x * w.x + a.y * w.y + a.z * w.z + a.w * w.w;
    }
#pragma unroll
    for (int off = 16; off > 0; off >>= 1)
        s += __shfl_xor_sync(0xffffffffu, s, off);

    if (lane == 0)
        g_gate[row] = 1.f / (1.f + __expf(-(s + bg[0])));
}

// ---------------------------------------------------------------------------
// Launch
// ---------------------------------------------------------------------------
extern "C" void kernel_launch(void* const* d_in, const int* in_sizes, int n_in,
                              void* d_out, int out_size)
{
    const float* q  = (const float*)d_in[0];
    const float* k  = (const float*)d_in[1];
    const float* v  = (const float*)d_in[2];
    const float* Wq = (const float*)d_in[3];
    const float* bq = (const float*)d_in[4];
    const float* Wk = (const float*)d_in[5];
    const float* bk = (const float*)d_in[6];
    const float* Wv = (const float*)d_in[7];
    const float* bv = (const float*)d_in[8];
    const float* Wo = (const float*)d_in[9];
    const float* bo = (const float*)d_in[10];
    const float* Wg = (const float*)d_in[11];
    const float* bg = (const float*)d_in[12];
    const float* Wp = (const float*)d_in[13];
    const float* bp = (const float*)d_in[14];
    (void)in_sizes; (void)n_in; (void)out_size;

    float* out  = (float*)d_out;                          // (L, D)
    float* Wout = out + (size_t)LSEQ * DMODEL;            // (3, H, L, L)

    float *pQ, *pK, *pV, *pCtx, *pCur;
    cudaGetSymbolAddress((void**)&pQ,   g_Q);
    cudaGetSymbolAddress((void**)&pK,   g_K);
    cudaGetSymbolAddress((void**)&pV,   g_V);
    cudaGetSymbolAddress((void**)&pCtx, g_ctx);
    cudaGetSymbolAddress((void**)&pCur, g_cur);

    const size_t smemScores = 2 * 64 * 132 * sizeof(float);  // 67.6 KB
    cudaFuncSetAttribute(scores_kernel,
                         cudaFuncAttributeMaxDynamicSharedMemorySize,
                         (int)smemScores);

    dim3 gProj(DMODEL / 64, LSEQ / 128);  // (16, 16)

    gates_kernel<<<LSEQ / 8, 256>>>(q, Wg, bg);
    gemm_proj<<<gProj, 256>>>(q, Wq, bq, pQ);
    gemm_proj<<<gProj, 256>>>(k, Wk, bk, pK);
    gemm_proj<<<gProj, 256>>>(v, Wv, bv, pV);

    const float* cur = pQ;
    for (int hop = 0; hop < NHOPS; hop++) {
        float* Sh = Wout + (size_t)hop * NH * LSEQ * LSEQ;
        dim3 gS(LSEQ / 128, LSEQ / 128, NH);
        scores_kernel<<<gS, 256, smemScores>>>(cur, pK, Sh);
        stats_kernel<<<NH * LSEQ / 8, 256>>>(Sh);
        dim3 gC(LSEQ / 128, NH);
        ctx_kernel<<<gC, 256>>>(Sh, pV);
        if (hop < NHOPS - 1) {
            gemm_proj<<<gProj, 256>>>(pCtx, Wp, bp, pCur);
            cur = pCur;
        }
    }
    gemm_proj<<<gProj, 256>>>(pCtx, Wo, bo, out);
}

// round 10
// speedup vs baseline: 1.0430x; 1.0430x over previous
#include <cuda_runtime.h>
#include <cstdint>

#define LSEQ   2048
#define DMODEL 1024
#define NH     16
#define DKH    64
#define NHOPS  3

typedef unsigned long long u64t;

// ---------------- f32x2 helpers (sm_100+ packed fp32, base ISA) ------------
__device__ __forceinline__ u64t f2pack(float lo, float hi) {
    u64t r; asm("mov.b64 %0, {%1, %2};" : "=l"(r) : "f"(lo), "f"(hi)); return r;
}
__device__ __forceinline__ void f2unpack(float& lo, float& hi, u64t v) {
    asm("mov.b64 {%0, %1}, %2;" : "=f"(lo), "=f"(hi) : "l"(v));
}
__device__ __forceinline__ void ffma2(u64t& d, u64t a, u64t b) {
    asm("fma.rn.f32x2 %0, %1, %2, %0;" : "+l"(d) : "l"(a), "l"(b));
}

// ---------------------------------------------------------------------------
// Scratch
// ---------------------------------------------------------------------------
__device__ float g_Q[LSEQ * DMODEL];
__device__ float g_K[LSEQ * DMODEL];
__device__ float g_V[LSEQ * DMODEL];
__device__ float g_ctx[LSEQ * DMODEL];
__device__ float g_cur[LSEQ * DMODEL];
__device__ float g_gate[LSEQ];
__device__ float g_rowscale[NH * LSEQ];  // gate[q] / sum(exp(s - m))

// ---------------------------------------------------------------------------
// Projection GEMM: C[2048][1024] = A @ B + bias. 128x64 tile, BK=8, 256 thr.
// f32x2: acc pairs over rows (contiguous in As), B broadcast-packed.
// ---------------------------------------------------------------------------
__global__ __launch_bounds__(256)
void gemm_proj(const float* __restrict__ A, const float* __restrict__ B,
               const float* __restrict__ bias, float* __restrict__ C)
{
    __shared__ float As[8][132];
    __shared__ float Bs[8][64];

    const int tid = threadIdx.x;
    const int tx  = tid & 15;
    const int ty  = tid >> 4;
    const int rowBase = blockIdx.y * 128;
    const int colBase = blockIdx.x * 64;

    const int aRow = tid >> 1;
    const int aCol = (tid & 1) * 4;
    const int bRow = tid >> 5;
    const int bCol = (tid & 31) * 2;

    const float* Aptr = A + (size_t)(rowBase + aRow) * DMODEL + aCol;
    const float* Bptr = B + (size_t)bRow * DMODEL + colBase + bCol;

    u64t accp[4][4];
#pragma unroll
    for (int p = 0; p < 4; p++)
#pragma unroll
        for (int j = 0; j < 4; j++) accp[p][j] = 0ull;

    float4 aReg = *(const float4*)Aptr;
    float2 bReg = *(const float2*)Bptr;

    const int NT = DMODEL / 8;
    for (int kt = 0; kt < NT; kt++) {
        As[aCol + 0][aRow] = aReg.x; As[aCol + 1][aRow] = aReg.y;
        As[aCol + 2][aRow] = aReg.z; As[aCol + 3][aRow] = aReg.w;
        *(float2*)&Bs[bRow][bCol] = bReg;
        __syncthreads();
        if (kt + 1 < NT) {
            aReg = *(const float4*)(Aptr + (kt + 1) * 8);
            bReg = *(const float2*)(Bptr + (size_t)(kt + 1) * 8 * DMODEL);
        }
#pragma unroll
        for (int k = 0; k < 8; k++) {
            const u64t* a0 = (const u64t*)&As[k][ty * 4];
            const u64t* a1 = (const u64t*)&As[k][64 + ty * 4];
            u64t ap[4] = {a0[0], a0[1], a1[0], a1[1]};
            float4 b = *(const float4*)&Bs[k][tx * 4];
            u64t bb[4] = {f2pack(b.x, b.x), f2pack(b.y, b.y),
                          f2pack(b.z, b.z), f2pack(b.w, b.w)};
#pragma unroll
            for (int p = 0; p < 4; p++)
#pragma unroll
                for (int j = 0; j < 4; j++)
                    ffma2(accp[p][j], ap[p], bb[j]);
        }
        __syncthreads();
    }

    const int c = colBase + tx * 4;
    float4 bv = *(const float4*)&bias[c];
#pragma unroll
    for (int p = 0; p < 4; p++) {
        float lo[4], hi[4];
#pragma unroll
        for (int j = 0; j < 4; j++) f2unpack(lo[j], hi[j], accp[p][j]);
        int r0 = rowBase + ((p < 2) ? (ty * 4 + p * 2) : (64 + ty * 4 + (p - 2) * 2));
        float4 o0 = {lo[0] + bv.x, lo[1] + bv.y, lo[2] + bv.z, lo[3] + bv.w};
        float4 o1 = {hi[0] + bv.x, hi[1] + bv.y, hi[2] + bv.z, hi[3] + bv.w};
        *(float4*)&C[(size_t)r0 * DMODEL + c]       = o0;
        *(float4*)&C[(size_t)(r0 + 1) * DMODEL + c] = o1;
    }
}

// ---------------------------------------------------------------------------
// Scores: S[h][q][k] = 0.125 * dot(cur[q,h*64..], K[k,h*64..]). 128x128, K=64.
// f32x2 row-paired accumulators.
// ---------------------------------------------------------------------------
__global__ __launch_bounds__(256)
void scores_kernel(const float* __restrict__ Qc, const float* __restrict__ Kc,
                   float* __restrict__ S)
{
    extern __shared__ float sm[];
    float (*As)[132] = (float(*)[132])sm;
    float (*Bs)[132] = (float(*)[132])(sm + 64 * 132);

    const int tid = threadIdx.x;
    const int tx = tid & 15;
    const int ty = tid >> 4;
    const int h = blockIdx.z;
    const int qBase = blockIdx.y * 128;
    const int kBase = blockIdx.x * 128;

    const float* Ap = Qc + (size_t)qBase * DMODEL + h * DKH;
    const float* Bp = Kc + (size_t)kBase * DMODEL + h * DKH;

#pragma unroll
    for (int i = 0; i < 8; i++) {
        int idx = tid + i * 256;
        int r   = idx >> 4;
        int c4  = (idx & 15) * 4;
        float4 a = *(const float4*)(Ap + (size_t)r * DMODEL + c4);
        As[c4 + 0][r] = a.x; As[c4 + 1][r] = a.y;
        As[c4 + 2][r] = a.z; As[c4 + 3][r] = a.w;
        float4 b = *(const float4*)(Bp + (size_t)r * DMODEL + c4);
        Bs[c4 + 0][r] = b.x; Bs[c4 + 1][r] = b.y;
        Bs[c4 + 2][r] = b.z; Bs[c4 + 3][r] = b.w;
    }
    __syncthreads();

    u64t accp[4][8];
#pragma unroll
    for (int p = 0; p < 4; p++)
#pragma unroll
        for (int j = 0; j < 8; j++) accp[p][j] = 0ull;

#pragma unroll 4
    for (int k = 0; k < 64; k++) {
        const u64t* a0 = (const u64t*)&As[k][ty * 4];
        const u64t* a1 = (const u64t*)&As[k][64 + ty * 4];
        u64t ap[4] = {a0[0], a0[1], a1[0], a1[1]};
        float4 b0 = *(const float4*)&Bs[k][tx * 4];
        float4 b1 = *(const float4*)&Bs[k][64 + tx * 4];
        u64t bb[8] = {f2pack(b0.x, b0.x), f2pack(b0.y, b0.y),
                      f2pack(b0.z, b0.z), f2pack(b0.w, b0.w),
                      f2pack(b1.x, b1.x), f2pack(b1.y, b1.y),
                      f2pack(b1.z, b1.z), f2pack(b1.w, b1.w)};
#pragma unroll
        for (int p = 0; p < 4; p++)
#pragma unroll
            for (int j = 0; j < 8; j++)
                ffma2(accp[p][j], ap[p], bb[j]);
    }

    const float sc = 0.125f;
    float* Sp = S + ((size_t)(h * LSEQ + qBase)) * LSEQ + kBase;
#pragma unroll
    for (int p = 0; p < 4; p++) {
        float lo[8], hi[8];
#pragma unroll
        for (int j = 0; j < 8; j++) f2unpack(lo[j], hi[j], accp[p][j]);
        int r0 = (p < 2) ? (ty * 4 + p * 2) : (64 + ty * 4 + (p - 2) * 2);
        float* d0 = &Sp[(size_t)r0 * LSEQ];
        float* d1 = &Sp[(size_t)(r0 + 1) * LSEQ];
        float4 v;
        v = make_float4(lo[0] * sc, lo[1] * sc, lo[2] * sc, lo[3] * sc);
        *(float4*)&d0[tx * 4] = v;
        v = make_float4(lo[4] * sc, lo[5] * sc, lo[6] * sc, lo[7] * sc);
        *(float4*)&d0[64 + tx * 4] = v;
        v = make_float4(hi[0] * sc, hi[1] * sc, hi[2] * sc, hi[3] * sc);
        *(float4*)&d1[tx * 4] = v;
        v = make_float4(hi[4] * sc, hi[5] * sc, hi[6] * sc, hi[7] * sc);
        *(float4*)&d1[64 + tx * 4] = v;
    }
}

// ---------------------------------------------------------------------------
// Row stats + in-place exp: one warp per (h,q) row held in registers.
// Computes m, writes e = exp(s-m) back IN PLACE, stores gate/sum.
// (exp computed exactly once per element; ctx only scales.)
// ---------------------------------------------------------------------------
__global__ __launch_bounds__(256)
void stats_kernel(float* __restrict__ S)
{
    const int warp = threadIdx.x >> 5;
    const int lane = threadIdx.x & 31;
    const int row = blockIdx.x * 8 + warp;
    float* p = S + (size_t)row * LSEQ;

    float4 vals[16];
    float m = -1e30f;
#pragma unroll
    for (int i = 0; i < 16; i++) {
        vals[i] = *(const float4*)&p[(lane + i * 32) * 4];
        m = fmaxf(m, fmaxf(fmaxf(vals[i].x, vals[i].y), fmaxf(vals[i].z, vals[i].w)));
    }
#pragma unroll
    for (int off = 16; off > 0; off >>= 1)
        m = fmaxf(m, __shfl_xor_sync(0xffffffffu, m, off));

    float s = 0.f;
#pragma unroll
    for (int i = 0; i < 16; i++) {
        float4 e;
        e.x = __expf(vals[i].x - m);
        e.y = __expf(vals[i].y - m);
        e.z = __expf(vals[i].z - m);
        e.w = __expf(vals[i].w - m);
        s += e.x + e.y + e.z + e.w;
        *(float4*)&p[(lane + i * 32) * 4] = e;
    }
#pragma unroll
    for (int off = 16; off > 0; off >>= 1)
        s += __shfl_xor_sync(0xffffffffu, s, off);

    if (lane == 0)
        g_rowscale[row] = g_gate[row & (LSEQ - 1)] / s;
}

// ---------------------------------------------------------------------------
// Fused scale + w write + ctx GEMM. S holds e = exp(s-m); w = e * (gate/sum).
// Writes w in-place (weights output) and accumulates ctx = w @ V with f32x2.
// ---------------------------------------------------------------------------
__global__ __launch_bounds__(256)
void ctx_kernel(float* __restrict__ S, const float* __restrict__ V)
{
    __shared__ float Ws[32][132];
    __shared__ float Vs[32][64];

    const int tid = threadIdx.x;
    const int tx = tid & 15;
    const int ty = tid >> 4;
    const int h = blockIdx.y;
    const int qBase = blockIdx.x * 128;

    const int sRow0 = tid >> 3;
    const int sCol  = (tid & 7) * 4;

    float gloc[4];
#pragma unroll
    for (int r = 0; r < 4; r++)
        gloc[r] = g_rowscale[h * LSEQ + qBase + sRow0 + 32 * r];

    float* Sbase = S + ((size_t)(h * LSEQ + qBase)) * LSEQ;
    const float* Vp = V + h * DKH;

    u64t accp[4][4];
#pragma unroll
    for (int p = 0; p < 4; p++)
#pragma unroll
        for (int j = 0; j < 4; j++) accp[p][j] = 0ull;

    float4 sreg[4];
    float4 vreg[2];
#pragma unroll
    for (int r = 0; r < 4; r++)
        sreg[r] = *(const float4*)&Sbase[(size_t)(sRow0 + 32 * r) * LSEQ + sCol];
#pragma unroll
    for (int i = 0; i < 2; i++) {
        int idx = tid + i * 256;
        int vr = idx >> 4, vc = (idx & 15) * 4;
        vreg[i] = *(const float4*)&Vp[(size_t)vr * DMODEL + vc];
    }

    const int NT = LSEQ / 32;
    for (int kt = 0; kt < NT; kt++) {
#pragma unroll
        for (int r = 0; r < 4; r++) {
            int row = sRow0 + 32 * r;
            float4 e = sreg[r];
            float4 w = {e.x * gloc[r], e.y * gloc[r], e.z * gloc[r], e.w * gloc[r]};
            *(float4*)&Sbase[(size_t)row * LSEQ + kt * 32 + sCol] = w;
            Ws[sCol + 0][row] = w.x; Ws[sCol + 1][row] = w.y;
            Ws[sCol + 2][row] = w.z; Ws[sCol + 3][row] = w.w;
        }
#pragma unroll
        for (int i = 0; i < 2; i++) {
            int idx = tid + i * 256;
            int vr = idx >> 4, vc = (idx & 15) * 4;
            *(float4*)&Vs[vr][vc] = vreg[i];
        }
        __syncthreads();
        if (kt + 1 < NT) {
#pragma unroll
            for (int r = 0; r < 4; r++)
                sreg[r] = *(const float4*)&Sbase[(size_t)(sRow0 + 32 * r) * LSEQ
                                                 + (kt + 1) * 32 + sCol];
#pragma unroll
            for (int i = 0; i < 2; i++) {
                int idx = tid + i * 256;
                int vr = idx >> 4, vc = (idx & 15) * 4;
                vreg[i] = *(const float4*)&Vp[(size_t)((kt + 1) * 32 + vr) * DMODEL + vc];
            }
        }
#pragma unroll 8
        for (int k = 0; k < 32; k++) {
            const u64t* a0 = (const u64t*)&Ws[k][ty * 4];
            const u64t* a1 = (const u64t*)&Ws[k][64 + ty * 4];
            u64t ap[4] = {a0[0], a0[1], a1[0], a1[1]};
            float4 b = *(const float4*)&Vs[k][tx * 4];
            u64t bb[4] = {f2pack(b.x, b.x), f2pack(b.y, b.y),
                          f2pack(b.z, b.z), f2pack(b.w, b.w)};
#pragma unroll
            for (int p = 0; p < 4; p++)
#pragma unroll
                for (int j = 0; j < 4; j++)
                    ffma2(accp[p][j], ap[p], bb[j]);
        }
        __syncthreads();
    }

#pragma unroll
    for (int p = 0; p < 4; p++) {
        float lo[4], hi[4];
#pragma unroll
        for (int j = 0; j < 4; j++) f2unpack(lo[j], hi[j], accp[p][j]);
        int r0 = qBase + ((p < 2) ? (ty * 4 + p * 2) : (64 + ty * 4 + (p - 2) * 2));
        *(float4*)&g_ctx[(size_t)r0 * DMODEL + h * DKH + tx * 4] =
            make_float4(lo[0], lo[1], lo[2], lo[3]);
        *(float4*)&g_ctx[(size_t)(r0 + 1) * DMODEL + h * DKH + tx * 4] =
            make_float4(hi[0], hi[1], hi[2], hi[3]);
    }
}

// ---------------------------------------------------------------------------
// Gate: g[q] = sigmoid(dot(q_row, Wg) + bg). One warp per row.
// ---------------------------------------------------------------------------
__global__ __launch_bounds__(256)
void gates_kernel(const float* __restrict__ q, const float* __restrict__ Wg,
                  const float* __restrict__ bg)
{
    const int warp = threadIdx.x >> 5;
    const int lane = threadIdx.x & 31;
    const int row = blockIdx.x * 8 + warp;
    const float* p = q + (size_t)row * DMODEL;

    float s = 0.f;
#pragma unroll
    for (int i = 0; i < 8; i++) {
        float4 a = *(const float4*)&p[(lane + i * 32) * 4];
        float4 w = *(const float4*)&Wg[(lane + i * 32) * 4];
        s += a.x * w.x + a.y * w.y + a.z * w.z + a.w * w.w;
    }
#pragma unroll
    for (int off = 16; off > 0; off >>= 1)
        s += __shfl_xor_sync(0xffffffffu, s, off);

    if (lane == 0)
        g_gate[row] = 1.f / (1.f + __expf(-(s + bg[0])));
}

// ---------------------------------------------------------------------------
// Launch
// ---------------------------------------------------------------------------
extern "C" void kernel_launch(void* const* d_in, const int* in_sizes, int n_in,
                              void* d_out, int out_size)
{
    const float* q  = (const float*)d_in[0];
    const float* k  = (const float*)d_in[1];
    const float* v  = (const float*)d_in[2];
    const float* Wq = (const float*)d_in[3];
    const float* bq = (const float*)d_in[4];
    const float* Wk = (const float*)d_in[5];
    const float* bk = (const float*)d_in[6];
    const float* Wv = (const float*)d_in[7];
    const float* bv = (const float*)d_in[8];
    const float* Wo = (const float*)d_in[9];
    const float* bo = (const float*)d_in[10];
    const float* Wg = (const float*)d_in[11];
    const float* bg = (const float*)d_in[12];
    const float* Wp = (const float*)d_in[13];
    const float* bp = (const float*)d_in[14];
    (void)in_sizes; (void)n_in; (void)out_size;

    float* out  = (float*)d_out;                          // (L, D)
    float* Wout = out + (size_t)LSEQ * DMODEL;            // (3, H, L, L)

    float *pQ, *pK, *pV, *pCtx, *pCur;
    cudaGetSymbolAddress((void**)&pQ,   g_Q);
    cudaGetSymbolAddress((void**)&pK,   g_K);
    cudaGetSymbolAddress((void**)&pV,   g_V);
    cudaGetSymbolAddress((void**)&pCtx, g_ctx);
    cudaGetSymbolAddress((void**)&pCur, g_cur);

    const size_t smemScores = 2 * 64 * 132 * sizeof(float);  // 67.6 KB
    cudaFuncSetAttribute(scores_kernel,
                         cudaFuncAttributeMaxDynamicSharedMemorySize,
                         (int)smemScores);

    dim3 gProj(DMODEL / 64, LSEQ / 128);  // (16, 16)

    gates_kernel<<<LSEQ / 8, 256>>>(q, Wg, bg);
    gemm_proj<<<gProj, 256>>>(q, Wq, bq, pQ);
    gemm_proj<<<gProj, 256>>>(k, Wk, bk, pK);
    gemm_proj<<<gProj, 256>>>(v, Wv, bv, pV);

    const float* cur = pQ;
    for (int hop = 0; hop < NHOPS; hop++) {
        float* Sh = Wout + (size_t)hop * NH * LSEQ * LSEQ;
        dim3 gS(LSEQ / 128, LSEQ / 128, NH);
        scores_kernel<<<gS, 256, smemScores>>>(cur, pK, Sh);
        stats_kernel<<<NH * LSEQ / 8, 256>>>(Sh);
        dim3 gC(LSEQ / 128, NH);
        ctx_kernel<<<gC, 256>>>(Sh, pV);
        if (hop < NHOPS - 1) {
            gemm_proj<<<gProj, 256>>>(pCtx, Wp, bp, pCur);
            cur = pCur;
        }
    }
    gemm_proj<<<gProj, 256>>>(pCtx, Wo, bo, out);
}